// round 12
// baseline (speedup 1.0000x reference)
#include <cuda_runtime.h>
#include <cuda_bf16.h>
#include <cstdint>

// SpatiallyJitterColorChannels: per-(b,c) 2D roll of x[64,3,512,512] fp32.
// out[b,c,h,w] = x[b,c,(h-sh)&511,(w-sw)&511], sh/sw = shifts[b,c,:]-2, |s|<=2.
//
// R12: R2's measured-best scheme + L2::256B fetch-granularity hint on loads.
//  - Dual adjacent aligned LDG.128 per output quad (duplicate B quad is an
//    L1 hit -> free) + per-plane-uniform register select o in {0..3}.
//  - ld.global.nc.L2::256B: read stream is perfectly sequential, so 256B L2
//    fills are lossless and halve the DRAM read-command count (longer
//    bursts at the HBM scheduler -- the only lever below the LTS).
//  - ILP=2, 256-thread blocks, 24576 CTAs (low edge of the measured band).

#define SHIFT 2

__device__ __forceinline__ float4 ldg_nc_256B(const float4* p) {
    float4 v;
    asm volatile("ld.global.nc.L2::256B.v4.f32 {%0,%1,%2,%3}, [%4];"
                 : "=f"(v.x), "=f"(v.y), "=f"(v.z), "=f"(v.w)
                 : "l"(p));
    return v;
}

__global__ void __launch_bounds__(256) roll2d_kernel(
    const float* __restrict__ x,
    const int*   __restrict__ shifts,   // [B, C, 2] int32 in [0, 2*SHIFT]
    float*       __restrict__ out)
{
    int base  = blockIdx.x * 512 + threadIdx.x;   // float4 index of element 0
    int plane = base >> 16;                       // / 65536 f4 per plane

    int sh = shifts[plane * 2 + 0] - SHIFT;
    int sw = shifts[plane * 2 + 1] - SHIFT;

    int qa_off, o;
    if (sw > 0) { qa_off = -4; o = 4 - sw; }      // o in {2,3}
    else        { qa_off = 0;  o = -sw;    }      // o in {0,1,2}

    const float* planep = x + ((size_t)plane << 18);   // * 262144

    float4 A[2], B[2];
    int    oidx[2];

    #pragma unroll
    for (int e = 0; e < 2; e++) {
        int idx    = base + e * 256;
        int within = idx & 65535;
        int h      = within >> 7;            // 128 f4 per row
        int w0     = (within & 127) << 2;    // starting column
        int hs     = (h - sh) & 511;
        const float* rowp = planep + (hs << 9);
        int qa = (w0 + qa_off) & 511;        // aligned quad, never straddles row
        int qb = (qa + 4) & 511;
        A[e] = ldg_nc_256B(reinterpret_cast<const float4*>(rowp + qa));
        B[e] = ldg_nc_256B(reinterpret_cast<const float4*>(rowp + qb));
        oidx[e] = idx;
    }

    #pragma unroll
    for (int e = 0; e < 2; e++) {
        float4 v;
        switch (o) {   // uniform per plane -> no divergence
            case 0:  v = A[e]; break;
            case 1:  v = make_float4(A[e].y, A[e].z, A[e].w, B[e].x); break;
            case 2:  v = make_float4(A[e].z, A[e].w, B[e].x, B[e].y); break;
            default: v = make_float4(A[e].w, B[e].x, B[e].y, B[e].z); break;
        }
        reinterpret_cast<float4*>(out)[oidx[e]] = v;
    }
}

extern "C" void kernel_launch(void* const* d_in, const int* in_sizes, int n_in,
                              void* d_out, int out_size)
{
    const float* x      = (const float*)d_in[0];
    const int*   shifts = (const int*)d_in[1];
    float*       out    = (float*)d_out;

    int n_f4   = out_size / 4;               // 12582912
    int blocks = n_f4 / 512;                 // 24576
    roll2d_kernel<<<blocks, 256>>>(x, shifts, out);
}

// round 13
// speedup vs baseline: 1.0126x; 1.0126x over previous
#include <cuda_runtime.h>
#include <cuda_bf16.h>
#include <cstdint>

// SpatiallyJitterColorChannels: per-(b,c) 2D roll of x[64,3,512,512] fp32.
// out[b,c,h,w] = x[b,c,(h-sh)&511,(w-sw)&511], sh/sw = shifts[b,c,:]-2, |s|<=2.
//
// FINAL — session best (63.5us, 6.25TB/s, rel_err 0; R2 configuration).
//  - Since |sw| <= 2, each output float4 lies within two ADJACENT aligned
//    source quads A,B. Load both with LDG.128 (B of thread t == A of thread
//    t+1 -> L1 hit; DRAM read traffic stays exact) and register-select.
//  - Select offset o = (sw>0 ? 4-sw : -sw) in {0..3} is uniform per plane:
//    non-divergent switch, pure register moves.
//  - ILP=2, 256 threads, 24576 blocks; blocks never straddle planes
//    (65536 f4/plane % 512 == 0) so shifts load once per thread.
//
// Ceiling evidence (12 measured rounds): request width {32,128,256-bit},
// shuffle-dedup, ILP {1,2,4}, cache policy {default, .cs, stwt, L2::256B},
// persistent grid-stride, block size {256,512} — every well-formed variant
// lands at 63.5-64.3us / 6.11-6.25TB/s with no SM pipe above 50%. That is
// this part's mixed read/write HBM streaming ceiling (~89% of 8TB/s spec on
// the required 402MB of traffic). No kernel-side lever remains.

#define SHIFT 2

__global__ void __launch_bounds__(256) roll2d_kernel(
    const float* __restrict__ x,
    const int*   __restrict__ shifts,   // [B, C, 2] int32 in [0, 2*SHIFT]
    float*       __restrict__ out)
{
    int base  = blockIdx.x * 512 + threadIdx.x;   // float4 index of element 0
    int plane = base >> 16;                       // / 65536 f4 per plane

    int sh = shifts[plane * 2 + 0] - SHIFT;
    int sw = shifts[plane * 2 + 1] - SHIFT;

    int qa_off, o;
    if (sw > 0) { qa_off = -4; o = 4 - sw; }      // o in {2,3}
    else        { qa_off = 0;  o = -sw;    }      // o in {0,1,2}

    const float* planep = x + ((size_t)plane << 18);   // * 262144

    float4 A[2], B[2];
    int    oidx[2];

    #pragma unroll
    for (int e = 0; e < 2; e++) {
        int idx    = base + e * 256;
        int within = idx & 65535;
        int h      = within >> 7;            // 128 f4 per row
        int w0     = (within & 127) << 2;    // starting column
        int hs     = (h - sh) & 511;
        const float* rowp = planep + (hs << 9);
        int qa = (w0 + qa_off) & 511;        // aligned quad, never straddles row
        int qb = (qa + 4) & 511;
        A[e] = *reinterpret_cast<const float4*>(rowp + qa);
        B[e] = *reinterpret_cast<const float4*>(rowp + qb);
        oidx[e] = idx;
    }

    #pragma unroll
    for (int e = 0; e < 2; e++) {
        float4 v;
        switch (o) {   // uniform per plane -> no divergence
            case 0:  v = A[e]; break;
            case 1:  v = make_float4(A[e].y, A[e].z, A[e].w, B[e].x); break;
            case 2:  v = make_float4(A[e].z, A[e].w, B[e].x, B[e].y); break;
            default: v = make_float4(A[e].w, B[e].x, B[e].y, B[e].z); break;
        }
        reinterpret_cast<float4*>(out)[oidx[e]] = v;
    }
}

extern "C" void kernel_launch(void* const* d_in, const int* in_sizes, int n_in,
                              void* d_out, int out_size)
{
    const float* x      = (const float*)d_in[0];
    const int*   shifts = (const int*)d_in[1];
    float*       out    = (float*)d_out;

    int n_f4   = out_size / 4;               // 12582912
    int blocks = n_f4 / 512;                 // 24576
    roll2d_kernel<<<blocks, 256>>>(x, shifts, out);
}